// round 6
// baseline (speedup 1.0000x reference)
#include <cuda_runtime.h>

#define BB 4
#define CC 3
#define TF 103
#define HH 224
#define WW 224
#define W4 (WW / 4)              // 56 float4 per row
#define FRAME4 (HH * W4)         // 12544 float4 per frame

// span-form rects per (b,t): {x0, x1-x0, y0, y1-y0}; membership: (u32)(p-p0) <= span
__device__ int4 g_self_rect[BB * TF];
__device__ int4 g_idx_rect[BB * TF];
__device__ int  g_index[BB];

__global__ void rect_kernel(const float* __restrict__ bbox,
                            const int* __restrict__ index) {
    int i = blockIdx.x * blockDim.x + threadIdx.x;
    if (i >= BB * TF) return;
    int b = i / TF;
    int t = i % TF;

    const float* p = bbox + (size_t)(b * TF + t) * 8;
    float xmn = fminf(fminf(p[0], p[2]), fminf(p[4], p[6]));
    float xmx = fmaxf(fmaxf(p[0], p[2]), fmaxf(p[4], p[6]));
    float ymn = fminf(fminf(p[1], p[3]), fminf(p[5], p[7]));
    float ymx = fmaxf(fmaxf(p[1], p[3]), fmaxf(p[5], p[7]));
    int x0 = (int)fmaxf(xmn, 0.0f);
    int x1 = (int)fminf(xmx, (float)WW);
    int y0 = (int)fmaxf(ymn, 0.0f);
    int y1 = (int)fminf(ymx, (float)HH);
    g_self_rect[i] = make_int4(x0, x1 - x0, y0, y1 - y0);

    int ib = index[b];
    const float* q = bbox + (size_t)(ib * TF + t) * 8;
    float xmn2 = fminf(fminf(q[0], q[2]), fminf(q[4], q[6]));
    float xmx2 = fmaxf(fmaxf(q[0], q[2]), fmaxf(q[4], q[6]));
    float ymn2 = fminf(fminf(q[1], q[3]), fminf(q[5], q[7]));
    float ymx2 = fmaxf(fmaxf(q[1], q[3]), fmaxf(q[5], q[7]));
    int ix0 = (int)xmn2, ix1 = (int)xmx2;
    int iy0 = (int)ymn2, iy1 = (int)ymx2;
    g_idx_rect[i] = make_int4(ix0, ix1 - ix0, iy0, iy1 - iy0);

    if (t == 0) g_index[b] = ib;
}

// grid = (HH/4, CC*TF, BB), block = (56, 4). One float4 per thread.
__global__ void __launch_bounds__(224)
fuse_kernel(const float4* __restrict__ v, float4* __restrict__ out) {
    int w4 = threadIdx.x;                       // 0..55
    int h  = (int)(blockIdx.x * 4 + threadIdx.y);
    unsigned int ct = blockIdx.y;               // c*TF + t
    unsigned int b  = blockIdx.z;

    unsigned int t  = ct % TF;
    int bt = (int)(b * TF + t);

    int4 rs = g_self_rect[bt];                  // x0, spanX, y0, spanY
    int4 ri = g_idx_rect[bt];
    unsigned int ib = (unsigned int)g_index[b];

    unsigned int planeOff = (unsigned int)(h * W4 + w4);
    unsigned int off  = (b  * (CC * TF) + ct) * FRAME4 + planeOff;
    unsigned int offI = (ib * (CC * TF) + ct) * FRAME4 + planeOff;

    int x = w4 * 4;
    int dxS = x - rs.x;
    int dxI = x - ri.x;
    bool rowS = (unsigned)(h - rs.z) <= (unsigned)rs.w;
    bool rowI = (unsigned)(h - ri.z) <= (unsigned)ri.w;

    // whole-float4 classification (span compares; underflow-safe for span<3)
    bool sAll = rowS & ((unsigned)dxS       <= (unsigned)(rs.y - 3));
    bool sAny = rowS & ((unsigned)(dxS + 3) <= (unsigned)(rs.y + 3));
    bool iAll = rowI & ((unsigned)dxI       <= (unsigned)(ri.y - 3));
    bool iAny = rowI & ((unsigned)(dxI + 3) <= (unsigned)(ri.y + 3));

    float4 o;
    if (sAll) {
        // fully inside self mask: pure copy
        o = __ldg(v + off);
    } else if (!sAny) {
        // no self contribution
        if (iAll) {
            o = make_float4(0.f, 0.f, 0.f, 0.f);       // fully blacked out
        } else if (!iAny) {
            o = __ldg(v + offI);                       // pure background copy
        } else {
            // idx-rect edge: background with per-component zeroing
            float4 vi = __ldg(v + offI);
            bool i0 = rowI & ((unsigned)(dxI    ) <= (unsigned)ri.y);
            bool i1 = rowI & ((unsigned)(dxI + 1) <= (unsigned)ri.y);
            bool i2 = rowI & ((unsigned)(dxI + 2) <= (unsigned)ri.y);
            bool i3 = rowI & ((unsigned)(dxI + 3) <= (unsigned)ri.y);
            o.x = i0 ? 0.f : vi.x;
            o.y = i1 ? 0.f : vi.y;
            o.z = i2 ? 0.f : vi.z;
            o.w = i3 ? 0.f : vi.w;
        }
    } else {
        // self-rect edge: general 3-way per component
        float4 vs = __ldg(v + off);
        float4 vi = __ldg(v + offI);
        bool m0 = rowS & ((unsigned)(dxS    ) <= (unsigned)rs.y);
        bool m1 = rowS & ((unsigned)(dxS + 1) <= (unsigned)rs.y);
        bool m2 = rowS & ((unsigned)(dxS + 2) <= (unsigned)rs.y);
        bool m3 = rowS & ((unsigned)(dxS + 3) <= (unsigned)rs.y);
        bool i0 = rowI & ((unsigned)(dxI    ) <= (unsigned)ri.y);
        bool i1 = rowI & ((unsigned)(dxI + 1) <= (unsigned)ri.y);
        bool i2 = rowI & ((unsigned)(dxI + 2) <= (unsigned)ri.y);
        bool i3 = rowI & ((unsigned)(dxI + 3) <= (unsigned)ri.y);
        o.x = m0 ? vs.x : (i0 ? 0.f : vi.x);
        o.y = m1 ? vs.y : (i1 ? 0.f : vi.y);
        o.z = m2 ? vs.z : (i2 ? 0.f : vi.z);
        o.w = m3 ? vs.w : (i3 ? 0.f : vi.w);
    }
    out[off] = o;
}

extern "C" void kernel_launch(void* const* d_in, const int* in_sizes, int n_in,
                              void* d_out, int out_size) {
    const float* video = (const float*)d_in[0];
    const float* bbox  = (const float*)d_in[1];
    const int*   index = (const int*)d_in[2];
    float* out = (float*)d_out;

    rect_kernel<<<2, 256>>>(bbox, index);
    dim3 grid(HH / 4, CC * TF, BB);
    dim3 block(W4, 4);
    fuse_kernel<<<grid, block>>>((const float4*)video, (float4*)out);
}

// round 7
// speedup vs baseline: 1.0885x; 1.0885x over previous
#include <cuda_runtime.h>

#define BB 4
#define CC 3
#define TF 103
#define HH 224
#define WW 224
#define W4 (WW / 4)                // 56 float4 per row
#define H2 (HH / 2)                // 112
#define FRAME4 (HH * W4)           // 12544
#define CT (CC * TF)               // 309
#define BLK 256
#define NTH (BB * CT * H2 * W4)    // 7,752,192
#define GRID (NTH / BLK)           // 30282 exact

// span-form rects per (b,t): {x0, x1-x0, y0, y1-y0}; membership: (u32)(p-p0) <= span
__device__ int4 g_self_rect[BB * TF];
__device__ int4 g_idx_rect[BB * TF];
__device__ int  g_index[BB];

__global__ void rect_kernel(const float* __restrict__ bbox,
                            const int* __restrict__ index) {
    int i = blockIdx.x * blockDim.x + threadIdx.x;
    if (i >= BB * TF) return;
    int b = i / TF;
    int t = i % TF;

    const float* p = bbox + (size_t)(b * TF + t) * 8;
    float xmn = fminf(fminf(p[0], p[2]), fminf(p[4], p[6]));
    float xmx = fmaxf(fmaxf(p[0], p[2]), fmaxf(p[4], p[6]));
    float ymn = fminf(fminf(p[1], p[3]), fminf(p[5], p[7]));
    float ymx = fmaxf(fmaxf(p[1], p[3]), fmaxf(p[5], p[7]));
    int x0 = (int)fmaxf(xmn, 0.0f);
    int x1 = (int)fminf(xmx, (float)WW);
    int y0 = (int)fmaxf(ymn, 0.0f);
    int y1 = (int)fminf(ymx, (float)HH);
    g_self_rect[i] = make_int4(x0, x1 - x0, y0, y1 - y0);

    int ib = index[b];
    const float* q = bbox + (size_t)(ib * TF + t) * 8;
    float xmn2 = fminf(fminf(q[0], q[2]), fminf(q[4], q[6]));
    float xmx2 = fmaxf(fmaxf(q[0], q[2]), fmaxf(q[4], q[6]));
    float ymn2 = fminf(fminf(q[1], q[3]), fminf(q[5], q[7]));
    float ymx2 = fmaxf(fmaxf(q[1], q[3]), fmaxf(q[5], q[7]));
    g_idx_rect[i] = make_int4((int)xmn2, (int)xmx2 - (int)xmn2,
                              (int)ymn2, (int)ymx2 - (int)ymn2);

    if (t == 0) g_index[b] = ib;
}

// Flat grid; thread handles (frame, h, w4) and (frame, h+112, w4).
// All control is predicated single-statement loads — no branch nests.
__global__ void __launch_bounds__(BLK, 6)
fuse_kernel(const float4* __restrict__ v, float4* __restrict__ out) {
    unsigned int i = blockIdx.x * (unsigned)BLK + threadIdx.x;

    unsigned int w4 = i % W4;
    unsigned int r  = i / W4;
    unsigned int h  = r % H2;          // 0..111
    unsigned int fr = r / H2;          // (b*CC + c)*TF + t
    unsigned int t  = fr % TF;
    unsigned int b  = fr / CT;

    int bt = (int)(b * TF + t);
    int4 rs = g_self_rect[bt];         // x0, spanX, y0, spanY
    int4 ri = g_idx_rect[bt];
    int ib = g_index[b];

    unsigned int off  = fr * FRAME4 + h * W4 + w4;
    unsigned int offI = off + (unsigned int)((ib - (int)b) * (CT * FRAME4));

    // column masks (shared by both rows)
    int x = (int)(w4 * 4);
    int dxS = x - rs.x;
    int dxI = x - ri.x;
    bool cS0 = (unsigned)(dxS    ) <= (unsigned)rs.y;
    bool cS1 = (unsigned)(dxS + 1) <= (unsigned)rs.y;
    bool cS2 = (unsigned)(dxS + 2) <= (unsigned)rs.y;
    bool cS3 = (unsigned)(dxS + 3) <= (unsigned)rs.y;
    bool cSany = cS0 | cS1 | cS2 | cS3;
    bool cI0 = (unsigned)(dxI    ) <= (unsigned)ri.y;
    bool cI1 = (unsigned)(dxI + 1) <= (unsigned)ri.y;
    bool cI2 = (unsigned)(dxI + 2) <= (unsigned)ri.y;
    bool cI3 = (unsigned)(dxI + 3) <= (unsigned)ri.y;

    int h0 = (int)h;
    int h1 = h0 + H2;
    bool rowS0 = (unsigned)(h0 - rs.z) <= (unsigned)rs.w;
    bool rowS1 = (unsigned)(h1 - rs.z) <= (unsigned)rs.w;
    bool rowI0 = (unsigned)(h0 - ri.z) <= (unsigned)ri.w;
    bool rowI1 = (unsigned)(h1 - ri.z) <= (unsigned)ri.w;

    // per-element masks
    bool m00 = rowS0 & cS0, m01 = rowS0 & cS1, m02 = rowS0 & cS2, m03 = rowS0 & cS3;
    bool m10 = rowS1 & cS0, m11 = rowS1 & cS1, m12 = rowS1 & cS2, m13 = rowS1 & cS3;
    bool q00 = rowI0 & cI0, q01 = rowI0 & cI1, q02 = rowI0 & cI2, q03 = rowI0 & cI3;
    bool q10 = rowI1 & cI0, q11 = rowI1 & cI1, q12 = rowI1 & cI2, q13 = rowI1 & cI3;

    bool needS0 = rowS0 & cSany;
    bool needS1 = rowS1 & cSany;
    bool needI0 = !((m00 | q00) & (m01 | q01) & (m02 | q02) & (m03 | q03));
    bool needI1 = !((m10 | q10) & (m11 | q11) & (m12 | q12) & (m13 | q13));

    // batch all predicated loads up front (MLP)
    float4 vs0 = make_float4(0.f, 0.f, 0.f, 0.f);
    float4 vs1 = make_float4(0.f, 0.f, 0.f, 0.f);
    float4 vi0 = make_float4(0.f, 0.f, 0.f, 0.f);
    float4 vi1 = make_float4(0.f, 0.f, 0.f, 0.f);
    if (needS0) vs0 = __ldg(v + off);
    if (needI0) vi0 = __ldg(v + offI);
    if (needS1) vs1 = __ldg(v + off  + H2 * W4);
    if (needI1) vi1 = __ldg(v + offI + H2 * W4);

    float4 o0, o1;
    o0.x = m00 ? vs0.x : (q00 ? 0.f : vi0.x);
    o0.y = m01 ? vs0.y : (q01 ? 0.f : vi0.y);
    o0.z = m02 ? vs0.z : (q02 ? 0.f : vi0.z);
    o0.w = m03 ? vs0.w : (q03 ? 0.f : vi0.w);
    o1.x = m10 ? vs1.x : (q10 ? 0.f : vi1.x);
    o1.y = m11 ? vs1.y : (q11 ? 0.f : vi1.y);
    o1.z = m12 ? vs1.z : (q12 ? 0.f : vi1.z);
    o1.w = m13 ? vs1.w : (q13 ? 0.f : vi1.w);

    out[off]           = o0;
    out[off + H2 * W4] = o1;
}

extern "C" void kernel_launch(void* const* d_in, const int* in_sizes, int n_in,
                              void* d_out, int out_size) {
    const float* video = (const float*)d_in[0];
    const float* bbox  = (const float*)d_in[1];
    const int*   index = (const int*)d_in[2];
    float* out = (float*)d_out;

    rect_kernel<<<2, 256>>>(bbox, index);
    fuse_kernel<<<GRID, BLK>>>((const float4*)video, (float4*)out);
}